// round 4
// baseline (speedup 1.0000x reference)
#include <cuda_runtime.h>
#include <cstddef>

// Raster_87205015978273: per-depo 10x10x10 Gaussian raster patches.
// Output buffer (all float32): [N*1000] rasters, then [N*3] offsets (exact
// integer values stored as float — harness compares the whole buffer as f32).
//
// Store-bandwidth-bound design: ~400MB of coalesced float4 streaming stores.

#define DPB 4        // depos per block
#define NTHREADS 256
#define PATCH 10

__global__ __launch_bounds__(NTHREADS, 8)
void raster_kernel(const float* __restrict__ sigma,   // [N,3]
                   const float* __restrict__ time,    // [N]
                   const float* __restrict__ charge,  // [N]
                   const float* __restrict__ tail,    // [N,3]
                   const float* __restrict__ gs,      // [3]
                   const float* __restrict__ nsig,    // [1]
                   float* __restrict__ out_r,         // [N,10,10,10] f32
                   float* __restrict__ out_o,         // [N,3] offsets as f32
                   int N)
{
    __shared__ float sw[DPB][32];    // [dl][d*10+j]: d=0 holds charge*wx, d=1 wy, d=2 wz
    __shared__ float pw[DPB][100];   // [dl][i*10+j] = charge*wx[i]*wy[j]

    const int t = threadIdx.x;
    const int base = blockIdx.x * DPB;

    // ---- Phase 1: per-dim cell integrals (30 per depo) + offsets ----
    if (t < DPB * 30) {
        const int dl = t / 30;
        const int r  = t - dl * 30;
        const int d  = r / 10;       // dim 0,1,2
        const int j  = r - d * 10;   // cell 0..9
        const int n  = base + dl;
        if (n < N) {
            // center = [tail[:,1], tail[:,2], time]
            float c = (d == 0) ? tail[3 * n + 1]
                    : (d == 1) ? tail[3 * n + 2]
                               : time[n];
            const float s  = sigma[3 * n + d];
            const float h  = gs[d];
            const float ns = nsig[0];

            const float imin = floorf((c - ns * s) / h);
            const float inv  = 1.0f / (1.41421356237309515f * s);
            const float e0 = (imin + (float)j) * h;
            const float e1 = (imin + (float)(j + 1)) * h;
            float w = 0.5f * (erff((e1 - c) * inv) - erff((e0 - c) * inv));
            if (d == 0) w *= charge[n];              // fold charge into x weights
            sw[dl][d * 10 + j] = w;
            if (j == 0) out_o[3 * n + d] = imin;     // offsets as float values
        }
    }
    __syncthreads();

    // ---- Phase 1.5: pw[i][j] = charge*wx[i]*wy[j] (400 values / block) ----
    #pragma unroll
    for (int p = t; p < DPB * 100; p += NTHREADS) {
        const int dl = p / 100;
        const int rr = p - dl * 100;
        const int i  = rr / 10;
        const int jj = rr - i * 10;
        pw[dl][rr] = sw[dl][i] * sw[dl][10 + jj];
    }
    __syncthreads();

    // ---- Phase 2: 1000 float4 coalesced streaming stores per block ----
    #pragma unroll
    for (int l = 0; l < 4; l++) {
        const int q = t + l * NTHREADS;    // 0..1023
        if (q >= DPB * 250) continue;      // only 1000 float4s per block
        const int dl = q / 250;
        const int q4 = q - dl * 250;       // float4 index within depo: 0..249
        const int n  = base + dl;
        if (n >= N) continue;
        const int e = q4 * 4;              // element index 0..996

        float4 v;
        {
            int i0 = e,     r0 = i0 / 10, k0 = i0 - 10 * r0;
            int i1 = e + 1, r1 = i1 / 10, k1 = i1 - 10 * r1;
            int i2 = e + 2, r2 = i2 / 10, k2 = i2 - 10 * r2;
            int i3 = e + 3, r3 = i3 / 10, k3 = i3 - 10 * r3;
            v.x = pw[dl][r0] * sw[dl][20 + k0];
            v.y = pw[dl][r1] * sw[dl][20 + k1];
            v.z = pw[dl][r2] * sw[dl][20 + k2];
            v.w = pw[dl][r3] * sw[dl][20 + k3];
        }
        *reinterpret_cast<float4*>(out_r + (size_t)n * 1000 + e) = v;
    }
}

extern "C" void kernel_launch(void* const* d_in, const int* in_sizes, int n_in,
                              void* d_out, int out_size)
{
    const float* sigma  = (const float*)d_in[0];
    const float* time   = (const float*)d_in[1];
    const float* charge = (const float*)d_in[2];
    const float* tail   = (const float*)d_in[3];
    const float* gs     = (const float*)d_in[4];
    const float* nsig   = (const float*)d_in[5];

    const int N = in_sizes[1];             // time has N elements
    float* out_r = (float*)d_out;
    float* out_o = out_r + (size_t)N * 1000;

    const int grid = (N + DPB - 1) / DPB;
    raster_kernel<<<grid, NTHREADS>>>(sigma, time, charge, tail, gs, nsig,
                                      out_r, out_o, N);
}

// round 6
// speedup vs baseline: 1.2163x; 1.2163x over previous
#include <cuda_runtime.h>
#include <cstddef>

// Raster_87205015978273: per-depo 10x10x10 Gaussian raster patches.
// Output buffer (all float32): [N*1000] rasters, then [N*3] offsets (exact
// integer values stored as float).
//
// R5: factor raster as (charge*wx[i]) * (wy[j]*wz[k]). Since 100 % 4 == 0,
// every aligned float4 of the patch sits in a single i-slab and is contiguous
// in the yz-plane -> per float4: 1 broadcast LDS + 1 LDS.128 + 4 FMUL + 1 STG.

#define DPB 4        // depos per block (one per 64-thread group)
#define NTHREADS 256

__global__ __launch_bounds__(NTHREADS, 8)
void raster_kernel(const float* __restrict__ sigma,   // [N,3]
                   const float* __restrict__ time,    // [N]
                   const float* __restrict__ charge,  // [N]
                   const float* __restrict__ tail,    // [N,3]
                   const float* __restrict__ gs,      // [3]
                   const float* __restrict__ nsig,    // [1]
                   float* __restrict__ out_r,         // [N,10,10,10] f32
                   float* __restrict__ out_o,         // [N,3] offsets as f32
                   int N)
{
    __shared__ float  sw[DPB][32];      // [dl][d*10+j]: d=0 -> charge*wx, d=1 wy, d=2 wz
    __shared__ float4 yz4[DPB][25];     // [dl][jk/4]: wy[j]*wz[k], jk = j*10+k

    const int t = threadIdx.x;
    const int base = blockIdx.x * DPB;

    // ---- Phase 1: per-dim cell integrals (30 per depo) + offsets ----
    if (t < DPB * 30) {
        const int dl = t / 30;
        const int r  = t - dl * 30;
        const int d  = r / 10;       // dim 0,1,2
        const int j  = r - d * 10;   // cell 0..9
        const int n  = base + dl;
        if (n < N) {
            // center = [tail[:,1], tail[:,2], time]
            float c = (d == 0) ? tail[3 * n + 1]
                    : (d == 1) ? tail[3 * n + 2]
                               : time[n];
            const float s  = sigma[3 * n + d];
            const float h  = gs[d];
            const float ns = nsig[0];

            const float imin = floorf((c - ns * s) / h);
            const float inv  = 1.0f / (1.41421356237309515f * s);
            const float e0 = (imin + (float)j) * h;
            const float e1 = (imin + (float)(j + 1)) * h;
            float w = 0.5f * (erff((e1 - c) * inv) - erff((e0 - c) * inv));
            if (d == 0) w *= charge[n];              // fold charge into x weights
            sw[dl][d * 10 + j] = w;
            if (j == 0) out_o[3 * n + d] = imin;     // offsets as float values
        }
    }
    __syncthreads();

    // ---- Phase 1.5: yz[jk] = wy[j]*wz[k] (400 values / block) ----
    {
        float* yzf = (float*)yz4;   // [DPB][100] flat
        #pragma unroll
        for (int p = t; p < DPB * 100; p += NTHREADS) {
            const int dl = p / 100;
            const int rr = p - dl * 100;
            const int jj = rr / 10;
            const int kk = rr - jj * 10;
            yzf[dl * 100 + rr] = sw[dl][10 + jj] * sw[dl][20 + kk];
        }
    }
    __syncthreads();

    // ---- Phase 2: 1000 coalesced float4 stores per block ----
    const int dl = t >> 6;            // warp-pair -> depo
    const int w  = t & 63;            // lane within depo group
    const int n  = base + dl;
    if (n < N) {
        float* dst = out_r + (size_t)n * 1000;
        #pragma unroll
        for (int l = 0; l < 4; l++) {
            const int q4 = w + (l << 6);          // float4 id 0..255
            if (l == 3 && q4 >= 250) break;       // only 250 float4s per depo
            const int i   = q4 / 25;              // x-slab (0..9)
            const int jk4 = q4 - i * 25;          // float4 index in yz plane

            const float  s = sw[dl][i];           // charge*wx[i] (broadcast)
            const float4 z = yz4[dl][jk4];
            float4 v = make_float4(s * z.x, s * z.y, s * z.z, s * z.w);
            *reinterpret_cast<float4*>(dst + q4 * 4) = v;
        }
    }
}

extern "C" void kernel_launch(void* const* d_in, const int* in_sizes, int n_in,
                              void* d_out, int out_size)
{
    const float* sigma  = (const float*)d_in[0];
    const float* time   = (const float*)d_in[1];
    const float* charge = (const float*)d_in[2];
    const float* tail   = (const float*)d_in[3];
    const float* gs     = (const float*)d_in[4];
    const float* nsig   = (const float*)d_in[5];

    const int N = in_sizes[1];             // time has N elements
    float* out_r = (float*)d_out;
    float* out_o = out_r + (size_t)N * 1000;

    const int grid = (N + DPB - 1) / DPB;
    raster_kernel<<<grid, NTHREADS>>>(sigma, time, charge, tail, gs, nsig,
                                      out_r, out_o, N);
}

// round 7
// speedup vs baseline: 1.4518x; 1.1936x over previous
#include <cuda_runtime.h>
#include <cstddef>

// Raster_87205015978273: per-depo 10x10x10 Gaussian raster patches.
// Output buffer (all float32): [N*1000] rasters, then [N*3] offsets (exact
// integer values stored as float).
//
// R7: batch phase 2 for MLP — issue all shared loads, then all FMULs, then
// all stores (streaming .cs hint). Branch-free tail via clamped index +
// predicated store.

#define DPB 4        // depos per block (one per 64-thread group)
#define NTHREADS 256

__global__ __launch_bounds__(NTHREADS, 8)
void raster_kernel(const float* __restrict__ sigma,   // [N,3]
                   const float* __restrict__ time,    // [N]
                   const float* __restrict__ charge,  // [N]
                   const float* __restrict__ tail,    // [N,3]
                   const float* __restrict__ gs,      // [3]
                   const float* __restrict__ nsig,    // [1]
                   float* __restrict__ out_r,         // [N,10,10,10] f32
                   float* __restrict__ out_o,         // [N,3] offsets as f32
                   int N)
{
    __shared__ float  sw[DPB][32];      // [dl][d*10+j]: d=0 -> charge*wx, d=1 wy, d=2 wz
    __shared__ float4 yz4[DPB][25];     // [dl][jk/4]: wy[j]*wz[k], jk = j*10+k

    const int t = threadIdx.x;
    const int base = blockIdx.x * DPB;

    // ---- Phase 1: per-dim cell integrals (30 per depo) + offsets ----
    if (t < DPB * 30) {
        const int dl = t / 30;
        const int r  = t - dl * 30;
        const int d  = r / 10;       // dim 0,1,2
        const int j  = r - d * 10;   // cell 0..9
        const int n  = base + dl;
        if (n < N) {
            // center = [tail[:,1], tail[:,2], time]
            float c = (d == 0) ? tail[3 * n + 1]
                    : (d == 1) ? tail[3 * n + 2]
                               : time[n];
            const float s  = sigma[3 * n + d];
            const float h  = gs[d];
            const float ns = nsig[0];

            const float imin = floorf((c - ns * s) / h);
            const float inv  = 1.0f / (1.41421356237309515f * s);
            const float e0 = (imin + (float)j) * h;
            const float e1 = (imin + (float)(j + 1)) * h;
            float w = 0.5f * (erff((e1 - c) * inv) - erff((e0 - c) * inv));
            if (d == 0) w *= charge[n];              // fold charge into x weights
            sw[dl][d * 10 + j] = w;
            if (j == 0) out_o[3 * n + d] = imin;     // offsets as float values
        }
    }
    __syncthreads();

    // ---- Phase 1.5: yz[jk] = wy[j]*wz[k] (400 values / block) ----
    {
        float* yzf = (float*)yz4;   // [DPB][100] flat
        #pragma unroll
        for (int p = t; p < DPB * 100; p += NTHREADS) {
            const int dl = p / 100;
            const int rr = p - dl * 100;
            const int jj = rr / 10;
            const int kk = rr - jj * 10;
            yzf[dl * 100 + rr] = sw[dl][10 + jj] * sw[dl][20 + kk];
        }
    }
    __syncthreads();

    // ---- Phase 2: 1000 coalesced float4 streaming stores per block,
    //      batched for MLP: all LDS first, then FMULs, then STGs. ----
    const int dl = t >> 6;            // warp-pair -> depo
    const int w  = t & 63;            // lane within depo group
    const int n  = base + dl;
    if (n < N) {
        float* dst = out_r + (size_t)n * 1000;

        float4 z[4];
        float  s[4];
        int    q4[4];

        #pragma unroll
        for (int l = 0; l < 4; l++) {
            int q = w + (l << 6);             // 0..255
            q4[l] = q;
            int qc = (q > 249) ? 249 : q;     // clamp tail (lanes 58..63 @ l=3)
            int i   = qc / 25;                // x-slab (0..9)
            int jk4 = qc - i * 25;            // float4 index in yz plane
            z[l] = yz4[dl][jk4];
            s[l] = sw[dl][i];                 // charge*wx[i] (broadcast)
        }

        float4 v[4];
        #pragma unroll
        for (int l = 0; l < 4; l++) {
            v[l].x = s[l] * z[l].x;
            v[l].y = s[l] * z[l].y;
            v[l].z = s[l] * z[l].z;
            v[l].w = s[l] * z[l].w;
        }

        #pragma unroll
        for (int l = 0; l < 4; l++) {
            if (l < 3 || q4[l] < 250) {
                __stcs(reinterpret_cast<float4*>(dst + q4[l] * 4), v[l]);
            }
        }
    }
}

extern "C" void kernel_launch(void* const* d_in, const int* in_sizes, int n_in,
                              void* d_out, int out_size)
{
    const float* sigma  = (const float*)d_in[0];
    const float* time   = (const float*)d_in[1];
    const float* charge = (const float*)d_in[2];
    const float* tail   = (const float*)d_in[3];
    const float* gs     = (const float*)d_in[4];
    const float* nsig   = (const float*)d_in[5];

    const int N = in_sizes[1];             // time has N elements
    float* out_r = (float*)d_out;
    float* out_o = out_r + (size_t)N * 1000;

    const int grid = (N + DPB - 1) / DPB;
    raster_kernel<<<grid, NTHREADS>>>(sigma, time, charge, tail, gs, nsig,
                                      out_r, out_o, N);
}

// round 8
// speedup vs baseline: 1.5504x; 1.0679x over previous
#include <cuda_runtime.h>
#include <cstddef>

// Raster_87205015978273: per-depo 10x10x10 Gaussian raster patches.
// Output buffer (all float32): [N*1000] rasters, then [N*3] offsets (exact
// integer values stored as float).
//
// R8: warp-per-depo. All phase sync is __syncwarp (no block barriers);
// 8 independent depos per block. Phase 2 stores batched 4-at-a-time with
// streaming (.cs) hint; fully coalesced 512B per warp-round.

#define DPB 8        // depos per block: one warp each
#define NTHREADS 256

__global__ __launch_bounds__(NTHREADS, 8)
void raster_kernel(const float* __restrict__ sigma,   // [N,3]
                   const float* __restrict__ time,    // [N]
                   const float* __restrict__ charge,  // [N]
                   const float* __restrict__ tail,    // [N,3]
                   const float* __restrict__ gs,      // [3]
                   const float* __restrict__ nsig,    // [1]
                   float* __restrict__ out_r,         // [N,10,10,10] f32
                   float* __restrict__ out_o,         // [N,3] offsets as f32
                   int N)
{
    __shared__ float  sw[DPB][32];      // [w][d*10+j]: d=0 -> charge*wx, d=1 wy, d=2 wz
    __shared__ float4 yz4[DPB][25];     // [w][jk/4]: wy[j]*wz[k], jk = j*10+k

    const int t    = threadIdx.x;
    const int wid  = t >> 5;            // warp = depo slot
    const int lane = t & 31;
    const int n    = blockIdx.x * DPB + wid;

    if (n < N) {
        // ---- Phase A: per-dim cell integrals (30 lanes) + offsets ----
        if (lane < 30) {
            const int d = lane / 10;     // dim 0,1,2
            const int j = lane - d * 10; // cell 0..9
            // center = [tail[:,1], tail[:,2], time]
            float c = (d == 0) ? tail[3 * n + 1]
                    : (d == 1) ? tail[3 * n + 2]
                               : time[n];
            const float s  = sigma[3 * n + d];
            const float h  = gs[d];
            const float ns = nsig[0];

            const float imin = floorf((c - ns * s) / h);
            const float inv  = 1.0f / (1.41421356237309515f * s);
            const float e0 = (imin + (float)j) * h;
            const float e1 = (imin + (float)(j + 1)) * h;
            float w = 0.5f * (erff((e1 - c) * inv) - erff((e0 - c) * inv));
            if (d == 0) w *= charge[n];              // fold charge into x weights
            sw[wid][d * 10 + j] = w;
            if (j == 0) out_o[3 * n + d] = imin;     // offsets as float values
        }
        __syncwarp();

        // ---- Phase B: yz[jk] = wy[j]*wz[k] (100 values per warp) ----
        {
            float* yzf = (float*)&yz4[wid][0];   // 100 floats
            #pragma unroll
            for (int l = 0; l < 4; l++) {
                const int p = lane + (l << 5);   // 0..127
                if (l < 3 || p < 100) {
                    const int jj = p / 10;
                    const int kk = p - jj * 10;
                    yzf[p] = sw[wid][10 + jj] * sw[wid][20 + kk];
                }
            }
        }
        __syncwarp();

        // ---- Phase C: 250 float4 streaming stores per warp, in 2 batches of 4 ----
        float* dst = out_r + (size_t)n * 1000;

        #pragma unroll
        for (int half = 0; half < 2; half++) {
            float4 z[4];
            float  s[4];
            int    q4[4];

            #pragma unroll
            for (int l = 0; l < 4; l++) {
                int q = lane + ((half * 4 + l) << 5);   // 0..255
                q4[l] = q;
                int qc = (q > 249) ? 249 : q;           // clamp tail
                int i   = qc / 25;                      // x-slab (0..9)
                int jk4 = qc - i * 25;                  // float4 index in yz plane
                z[l] = yz4[wid][jk4];
                s[l] = sw[wid][i];                      // charge*wx[i]
            }

            float4 v[4];
            #pragma unroll
            for (int l = 0; l < 4; l++) {
                v[l].x = s[l] * z[l].x;
                v[l].y = s[l] * z[l].y;
                v[l].z = s[l] * z[l].z;
                v[l].w = s[l] * z[l].w;
            }

            #pragma unroll
            for (int l = 0; l < 4; l++) {
                if (half == 0 || l < 3 || q4[l] < 250) {
                    __stcs(reinterpret_cast<float4*>(dst + q4[l] * 4), v[l]);
                }
            }
        }
    }
}

extern "C" void kernel_launch(void* const* d_in, const int* in_sizes, int n_in,
                              void* d_out, int out_size)
{
    const float* sigma  = (const float*)d_in[0];
    const float* time   = (const float*)d_in[1];
    const float* charge = (const float*)d_in[2];
    const float* tail   = (const float*)d_in[3];
    const float* gs     = (const float*)d_in[4];
    const float* nsig   = (const float*)d_in[5];

    const int N = in_sizes[1];             // time has N elements
    float* out_r = (float*)d_out;
    float* out_o = out_r + (size_t)N * 1000;

    const int grid = (N + DPB - 1) / DPB;
    raster_kernel<<<grid, NTHREADS>>>(sigma, time, charge, tail, gs, nsig,
                                      out_r, out_o, N);
}

// round 9
// speedup vs baseline: 1.5512x; 1.0005x over previous
#include <cuda_runtime.h>
#include <cstddef>

// Raster_87205015978273: per-depo 10x10x10 Gaussian raster patches.
// Output buffer (all float32): [N*1000] rasters, then [N*3] offsets (exact
// integer values stored as float).
//
// R9: warp-per-depo + 8-deep store batch. All 8 rounds' shared loads hoisted
// (MLP=8), in-place multiply, then 8 back-to-back STG.128 (.cs) per warp.
// launch_bounds(256,4) gives the register budget (~52 regs); occupancy is
// deliberately traded for in-flight store depth.

#define DPB 8        // depos per block: one warp each
#define NTHREADS 256

__global__ __launch_bounds__(NTHREADS, 4)
void raster_kernel(const float* __restrict__ sigma,   // [N,3]
                   const float* __restrict__ time,    // [N]
                   const float* __restrict__ charge,  // [N]
                   const float* __restrict__ tail,    // [N,3]
                   const float* __restrict__ gs,      // [3]
                   const float* __restrict__ nsig,    // [1]
                   float* __restrict__ out_r,         // [N,10,10,10] f32
                   float* __restrict__ out_o,         // [N,3] offsets as f32
                   int N)
{
    __shared__ float  sw[DPB][32];      // [w][d*10+j]: d=0 -> charge*wx, d=1 wy, d=2 wz
    __shared__ float4 yz4[DPB][25];     // [w][jk/4]: wy[j]*wz[k], jk = j*10+k

    const int t    = threadIdx.x;
    const int wid  = t >> 5;            // warp = depo slot
    const int lane = t & 31;
    const int n    = blockIdx.x * DPB + wid;

    if (n < N) {
        // ---- Phase A: per-dim cell integrals (30 lanes) + offsets ----
        if (lane < 30) {
            const int d = lane / 10;     // dim 0,1,2
            const int j = lane - d * 10; // cell 0..9
            // center = [tail[:,1], tail[:,2], time]
            float c = (d == 0) ? tail[3 * n + 1]
                    : (d == 1) ? tail[3 * n + 2]
                               : time[n];
            const float s  = sigma[3 * n + d];
            const float h  = gs[d];
            const float ns = nsig[0];

            const float imin = floorf((c - ns * s) / h);
            const float inv  = 1.0f / (1.41421356237309515f * s);
            const float e0 = (imin + (float)j) * h;
            const float e1 = (imin + (float)(j + 1)) * h;
            float w = 0.5f * (erff((e1 - c) * inv) - erff((e0 - c) * inv));
            if (d == 0) w *= charge[n];              // fold charge into x weights
            sw[wid][d * 10 + j] = w;
            if (j == 0) out_o[3 * n + d] = imin;     // offsets as float values
        }
        __syncwarp();

        // ---- Phase B: yz[jk] = wy[j]*wz[k] (100 values per warp) ----
        {
            float* yzf = (float*)&yz4[wid][0];   // 100 floats
            #pragma unroll
            for (int l = 0; l < 4; l++) {
                const int p = lane + (l << 5);   // 0..127
                if (l < 3 || p < 100) {
                    const int jj = p / 10;
                    const int kk = p - jj * 10;
                    yzf[p] = sw[wid][10 + jj] * sw[wid][20 + kk];
                }
            }
        }
        __syncwarp();

        // ---- Phase C: 250 float4 streaming stores per warp.
        //      All 8 rounds' shared loads hoisted (MLP=8), in-place FMUL,
        //      then 8 back-to-back STG.128. ----
        float* dst = out_r + (size_t)n * 1000;

        float4 z[8];
        float  s[8];

        #pragma unroll
        for (int l = 0; l < 8; l++) {
            int q  = lane + (l << 5);             // 0..255
            int qc = (q > 249) ? 249 : q;         // clamp tail (l=7, lanes 26..31)
            int i   = qc / 25;                    // x-slab (0..9)
            int jk4 = qc - i * 25;                // float4 index in yz plane
            z[l] = yz4[wid][jk4];
            s[l] = sw[wid][i];                    // charge*wx[i]
        }

        #pragma unroll
        for (int l = 0; l < 8; l++) {
            z[l].x *= s[l];
            z[l].y *= s[l];
            z[l].z *= s[l];
            z[l].w *= s[l];
        }

        #pragma unroll
        for (int l = 0; l < 8; l++) {
            int q = lane + (l << 5);
            if (l < 7 || q < 250) {
                __stcs(reinterpret_cast<float4*>(dst + q * 4), z[l]);
            }
        }
    }
}

extern "C" void kernel_launch(void* const* d_in, const int* in_sizes, int n_in,
                              void* d_out, int out_size)
{
    const float* sigma  = (const float*)d_in[0];
    const float* time   = (const float*)d_in[1];
    const float* charge = (const float*)d_in[2];
    const float* tail   = (const float*)d_in[3];
    const float* gs     = (const float*)d_in[4];
    const float* nsig   = (const float*)d_in[5];

    const int N = in_sizes[1];             // time has N elements
    float* out_r = (float*)d_out;
    float* out_o = out_r + (size_t)N * 1000;

    const int grid = (N + DPB - 1) / DPB;
    raster_kernel<<<grid, NTHREADS>>>(sigma, time, charge, tail, gs, nsig,
                                      out_r, out_o, N);
}